// round 11
// baseline (speedup 1.0000x reference)
#include <cuda_runtime.h>
#include <cuda_bf16.h>
#include <cstdint>

#define Bq 4
#define Sq 4096
#define Eq 1024
#define Hq 64

// bf16 hi/lo split Q,K,V scratch (qkv_kernel -> attn_kernel)
__device__ __nv_bfloat16 g_Qh[Bq * Sq * Hq];
__device__ __nv_bfloat16 g_Ql[Bq * Sq * Hq];
__device__ __nv_bfloat16 g_Kh[Bq * Sq * Hq];
__device__ __nv_bfloat16 g_Kl[Bq * Sq * Hq];
__device__ __nv_bfloat16 g_Vh[Bq * Sq * Hq];
__device__ __nv_bfloat16 g_Vl[Bq * Sq * Hq];
// pre-converted weights, [w][k][n] bf16 hi/lo
__device__ __nv_bfloat16 g_Wh[3 * Eq * Hq];
__device__ __nv_bfloat16 g_Wl[3 * Eq * Hq];

// ---- cp.async helpers ----
__device__ __forceinline__ void cpasync16(uint32_t dst, const void* src) {
    asm volatile("cp.async.cg.shared.global [%0], [%1], 16;" :: "r"(dst), "l"(src));
}
__device__ __forceinline__ void cpasync_commit() {
    asm volatile("cp.async.commit_group;");
}
__device__ __forceinline__ void cpasync_wait0() {
    asm volatile("cp.async.wait_group 0;");
}

// SW128-style swizzle on byte offsets within 128B-row bf16 tiles
__device__ __forceinline__ uint32_t sw128(uint32_t byte_off) {
    return byte_off ^ ((byte_off >> 3) & 0x70);
}

// ---- warp-level MMA helpers ----
__device__ __forceinline__ void ldmx4(uint32_t* r, uint32_t addr) {
    asm volatile("ldmatrix.sync.aligned.m8n8.x4.shared.b16 {%0,%1,%2,%3}, [%4];"
                 : "=r"(r[0]), "=r"(r[1]), "=r"(r[2]), "=r"(r[3]) : "r"(addr));
}
__device__ __forceinline__ void ldmx4t(uint32_t* r, uint32_t addr) {
    asm volatile("ldmatrix.sync.aligned.m8n8.x4.trans.shared.b16 {%0,%1,%2,%3}, [%4];"
                 : "=r"(r[0]), "=r"(r[1]), "=r"(r[2]), "=r"(r[3]) : "r"(addr));
}
__device__ __forceinline__ void mma_bf16(float* c, const uint32_t* a,
                                         uint32_t b0, uint32_t b1) {
    asm volatile(
        "mma.sync.aligned.m16n8k16.row.col.f32.bf16.bf16.f32 "
        "{%0,%1,%2,%3}, {%4,%5,%6,%7}, {%8,%9}, {%0,%1,%2,%3};"
        : "+f"(c[0]), "+f"(c[1]), "+f"(c[2]), "+f"(c[3])
        : "r"(a[0]), "r"(a[1]), "r"(a[2]), "r"(a[3]), "r"(b0), "r"(b1));
}
__device__ __forceinline__ uint32_t bfpack(float a, float b) {
    uint32_t r;
    asm("cvt.rn.bf16x2.f32 %0, %1, %2;" : "=r"(r) : "f"(b), "f"(a));
    return r;
}
__device__ __forceinline__ float bfround(float a) {
    return __bfloat162float(__float2bfloat16(a));
}

// ============================================================================
// Kernel 0: one-time W fp32 -> bf16 hi/lo, [w][k][n]. One float4 per thread.
// ============================================================================
__global__ __launch_bounds__(512) void wprep_kernel(
    const float* __restrict__ Wq, const float* __restrict__ Wk,
    const float* __restrict__ Wv)
{
    const float* Ws[3] = { Wq, Wk, Wv };
    int i = blockIdx.x * 512 + threadIdx.x;       // 0..49151 float4 slots
    int w = i / (Eq * Hq / 4);
    int rem = i - w * (Eq * Hq / 4);
    int k = rem >> 4;
    int n = (rem & 15) * 4;
    float4 v = *(const float4*)&Ws[w][(size_t)k * Hq + n];
    float h0 = bfround(v.x), h1 = bfround(v.y), h2 = bfround(v.z), h3 = bfround(v.w);
    uint2 hv = { bfpack(h0, h1), bfpack(h2, h3) };
    uint2 lv = { bfpack(v.x - h0, v.y - h1), bfpack(v.z - h2, v.w - h3) };
    size_t o = (size_t)w * Eq * Hq + (size_t)k * Hq + n;
    *(uint2*)&g_Wh[o] = hv;
    *(uint2*)&g_Wl[o] = lv;
}

// ============================================================================
// Kernel 1: fused QKV projection via HMMA bf16 3-term split (unchanged).
// ============================================================================
#define QKV_SMEM 81920

__global__ __launch_bounds__(256, 1)
void qkv_kernel(const float* __restrict__ x)
{
    extern __shared__ char qsm[];
    char* Ahi = qsm;
    char* Alo = qsm + 16384;
    const uint32_t uAhi = (uint32_t)__cvta_generic_to_shared(Ahi);
    const uint32_t uAlo = (uint32_t)__cvta_generic_to_shared(Alo);
    const uint32_t uBhi = uAhi + 32768;
    const uint32_t uBlo = uAhi + 57344;

    const int tid    = threadIdx.x;
    const int wid    = tid >> 5;
    const int lane   = tid & 31;
    const int m0     = blockIdx.x * 128;
    const int warp_m = wid & 3;
    const int warp_n = wid >> 2;
    const int g  = lane >> 3;
    const int lr = lane & 7;

    float c[2][12][4];
    #pragma unroll
    for (int mt = 0; mt < 2; mt++)
        #pragma unroll
        for (int nt = 0; nt < 12; nt++)
            #pragma unroll
            for (int e = 0; e < 4; e++) c[mt][nt][e] = 0.0f;

    #pragma unroll 1
    for (int ch = 0; ch < 16; ch++) {
        const int k0 = ch * 64;

        #pragma unroll
        for (int it = 0; it < 6; it++) {
            int cidx = tid + it * 256;
            int w   = cidx >> 9;
            int r   = (cidx >> 3) & 63;
            int c16 = cidx & 7;
            uint32_t off = (uint32_t)(w * 8192) + sw128((uint32_t)(r * 128 + c16 * 16));
            size_t src = (size_t)w * Eq * Hq + (size_t)(k0 + r) * Hq + c16 * 8;
            cpasync16(uBhi + off, g_Wh + src);
            cpasync16(uBlo + off, g_Wl + src);
        }
        cpasync_commit();

        {
            float2 va[16];
            #pragma unroll
            for (int i = 0; i < 16; i++) {
                int p = tid + i * 256;
                int r = p >> 5, k = (p & 31) * 2;
                va[i] = *(const float2*)&x[(size_t)(m0 + r) * Eq + k0 + k];
            }
            #pragma unroll
            for (int i = 0; i < 16; i++) {
                int p = tid + i * 256;
                int r = p >> 5, k = (p & 31) * 2;
                float h0 = bfround(va[i].x), h1 = bfround(va[i].y);
                uint32_t off = sw128((uint32_t)(r * 128 + k * 2));
                *(uint32_t*)(Ahi + off) = bfpack(h0, h1);
                *(uint32_t*)(Alo + off) = bfpack(va[i].x - h0, va[i].y - h1);
            }
        }
        cpasync_wait0();
        __syncthreads();

        #pragma unroll
        for (int ks = 0; ks < 4; ks++) {
            uint32_t ah[2][4], al[2][4];
            #pragma unroll
            for (int mt = 0; mt < 2; mt++) {
                int row = warp_m * 32 + mt * 16 + lr + ((g & 1) << 3);
                uint32_t off = sw128((uint32_t)(row * 128 + ((g >> 1) << 4) + ks * 32));
                ldmx4(ah[mt], uAhi + off);
                ldmx4(al[mt], uAlo + off);
            }
            #pragma unroll
            for (int np = 0; np < 6; np++) {
                const int nglob = warp_n * 96 + np * 16;
                const int w     = nglob >> 6;
                const int ncol  = nglob & 63;
                int krow = ks * 16 + ((g & 1) << 3) + lr;
                uint32_t off = sw128((uint32_t)(krow * 128 + (ncol + ((g >> 1) << 3)) * 2));
                uint32_t bh[4], bl[4];
                ldmx4t(bh, uBhi + w * 8192 + off);
                ldmx4t(bl, uBlo + w * 8192 + off);
                #pragma unroll
                for (int mt = 0; mt < 2; mt++) {
                    mma_bf16(c[mt][np * 2],     ah[mt], bh[0], bh[1]);
                    mma_bf16(c[mt][np * 2],     al[mt], bh[0], bh[1]);
                    mma_bf16(c[mt][np * 2],     ah[mt], bl[0], bl[1]);
                    mma_bf16(c[mt][np * 2 + 1], ah[mt], bh[2], bh[3]);
                    mma_bf16(c[mt][np * 2 + 1], al[mt], bh[2], bh[3]);
                    mma_bf16(c[mt][np * 2 + 1], ah[mt], bl[2], bl[3]);
                }
            }
        }
        __syncthreads();
    }

    {
        __nv_bfloat16* outsH[3] = { g_Qh, g_Kh, g_Vh };
        __nv_bfloat16* outsL[3] = { g_Ql, g_Kl, g_Vl };
        const int crow = lane >> 2;
        const int ccol = (lane & 3) * 2;
        #pragma unroll
        for (int nt = 0; nt < 12; nt++) {
            const int nglob = warp_n * 96 + nt * 8 + ccol;
            __nv_bfloat16* dh = outsH[nglob >> 6];
            __nv_bfloat16* dl = outsL[nglob >> 6];
            const int h = nglob & 63;
            #pragma unroll
            for (int mt = 0; mt < 2; mt++) {
                const int mrow = m0 + warp_m * 32 + mt * 16 + crow;
                #pragma unroll
                for (int rr = 0; rr < 2; rr++) {
                    float v0 = c[mt][nt][rr * 2 + 0];
                    float v1 = c[mt][nt][rr * 2 + 1];
                    float h0 = bfround(v0), h1 = bfround(v1);
                    size_t o = (size_t)(mrow + rr * 8) * Hq + h;
                    *(uint32_t*)&dh[o] = bfpack(h0, h1);
                    *(uint32_t*)&dl[o] = bfpack(v0 - h0, v1 - h1);
                }
            }
        }
    }
}

// ============================================================================
// Kernel 2: causal flash attention, FA2-style warp-local HMMA.
// 128 threads, 4 warps; warp owns 16 rows x ALL 64 kv cols -> stats fully
// warp-local (quad shuffles). P stays in registers (C-frag == A-frag layout).
// One __syncthreads per kv-iter. Br=Bc=64. 2 CTAs/SM (80KB smem each).
// Grid (64,4): qt = 63 - blockIdx.x (largest first).
// ============================================================================
// smem: QH 0 (8K), QL 8K; stage s at 16384+s*32768: KH+0 KL+8K VH+16K VL+24K
#define ATTN_SMEM 81920

__global__ __launch_bounds__(128, 2) void attn_kernel(float* __restrict__ out)
{
    extern __shared__ char smb[];
    const uint32_t base = (uint32_t)__cvta_generic_to_shared(smb);
    const uint32_t uQH = base, uQL = base + 8192;

    const int tid  = threadIdx.x;
    const int lane = tid & 31;
    const int wid  = tid >> 5;
    const int g    = lane >> 3;
    const int lr   = lane & 7;
    const int r0   = lane >> 2;
    const int cc   = (lane & 3) * 2;
    const int b    = blockIdx.y;
    const int qt   = 63 - (int)blockIdx.x;

    const int rowA = wid * 16 + r0;     // local q row (frag rows A / B=+8)

    const size_t qoff   = ((size_t)b * Sq + (size_t)qt * 64) * Hq;
    const size_t kvbase = (size_t)b * Sq * Hq;

    // ---- prologue: Q hi/lo + kv-tile 0 into stage 0 ----
    #pragma unroll
    for (int it = 0; it < 4; it++) {
        int chunk = tid + it * 128;         // 0..511: r=chunk>>3, c16=chunk&7
        int r = chunk >> 3, c16 = chunk & 7;
        uint32_t off = sw128((uint32_t)(r * 128 + c16 * 16));
        size_t gsrc = (size_t)r * 64 + c16 * 8;
        cpasync16(uQH + off, g_Qh + qoff + gsrc);
        cpasync16(uQL + off, g_Ql + qoff + gsrc);
        uint32_t st0 = base + 16384;
        cpasync16(st0 +     0 + off, g_Kh + kvbase + gsrc);
        cpasync16(st0 +  8192 + off, g_Kl + kvbase + gsrc);
        cpasync16(st0 + 16384 + off, g_Vh + kvbase + gsrc);
        cpasync16(st0 + 24576 + off, g_Vl + kvbase + gsrc);
    }
    cpasync_commit();
    cpasync_wait0();
    __syncthreads();

    // ---- hoist Q fragments (invariant across kv loop) ----
    uint32_t qh[4][4], ql[4][4];
    #pragma unroll
    for (int ks = 0; ks < 4; ks++) {
        int row = wid * 16 + lr + ((g & 1) << 3);
        uint32_t off = sw128((uint32_t)(row * 128 + ((g >> 1) << 4) + ks * 32));
        ldmx4(qh[ks], uQH + off);
        ldmx4(ql[ks], uQL + off);
    }

    float m0f = -1e30f, m1f = -1e30f, l0f = 0.0f, l1f = 0.0f;
    float o[8][4];
    #pragma unroll
    for (int np = 0; np < 8; np++)
        #pragma unroll
        for (int e = 0; e < 4; e++) o[np][e] = 0.0f;

    const float SCL = 0.125f * 1.44269504089f;

    #pragma unroll 1
    for (int ck = 0; ck <= qt; ck++) {
        const uint32_t st = base + 16384 + (uint32_t)(ck & 1) * 32768;
        const uint32_t kh = st, kl = st + 8192, vh = st + 16384, vl = st + 24576;

        if (ck < qt) {   // prefetch next kv tile into alternate stage
            const uint32_t sn = base + 16384 + (uint32_t)(1 - (ck & 1)) * 32768;
            size_t nsrc = kvbase + (size_t)(ck + 1) * 64 * Hq;
            #pragma unroll
            for (int it = 0; it < 4; it++) {
                int chunk = tid + it * 128;
                int r = chunk >> 3, c16 = chunk & 7;
                uint32_t off = sw128((uint32_t)(r * 128 + c16 * 16));
                size_t gsrc = (size_t)r * 64 + c16 * 8;
                cpasync16(sn +     0 + off, g_Kh + nsrc + gsrc);
                cpasync16(sn +  8192 + off, g_Kl + nsrc + gsrc);
                cpasync16(sn + 16384 + off, g_Vh + nsrc + gsrc);
                cpasync16(sn + 24576 + off, g_Vl + nsrc + gsrc);
            }
            cpasync_commit();
        }

        // ---- S = Q K^T : warp computes 16 rows x 64 cols ----
        float s[8][4];
        #pragma unroll
        for (int np = 0; np < 8; np++)
            #pragma unroll
            for (int e = 0; e < 4; e++) s[np][e] = 0.0f;

        #pragma unroll
        for (int ks = 0; ks < 4; ks++) {
            #pragma unroll
            for (int ng = 0; ng < 4; ng++) {
                int nrow = ng * 16 + ((g >> 1) << 3) + lr;
                uint32_t off = sw128((uint32_t)(nrow * 128 + ((g & 1) << 4) + ks * 32));
                uint32_t bh[4], bl[4];
                ldmx4(bh, kh + off);
                ldmx4(bl, kl + off);
                mma_bf16(s[ng * 2],     qh[ks], bh[0], bh[1]);
                mma_bf16(s[ng * 2],     ql[ks], bh[0], bh[1]);
                mma_bf16(s[ng * 2],     qh[ks], bl[0], bl[1]);
                mma_bf16(s[ng * 2 + 1], qh[ks], bh[2], bh[3]);
                mma_bf16(s[ng * 2 + 1], ql[ks], bh[2], bh[3]);
                mma_bf16(s[ng * 2 + 1], qh[ks], bl[2], bl[3]);
            }
        }

        // ---- scale + causal mask (diagonal tile only) ----
        if (ck == qt) {
            const int gi0 = rowA;           // same tile => local rows/cols
            const int gi1 = rowA + 8;
            #pragma unroll
            for (int np = 0; np < 8; np++) {
                int gj = np * 8 + cc;
                s[np][0] = (gj     > gi0) ? -1e30f : s[np][0] * SCL;
                s[np][1] = (gj + 1 > gi0) ? -1e30f : s[np][1] * SCL;
                s[np][2] = (gj     > gi1) ? -1e30f : s[np][2] * SCL;
                s[np][3] = (gj + 1 > gi1) ? -1e30f : s[np][3] * SCL;
            }
        } else {
            #pragma unroll
            for (int np = 0; np < 8; np++)
                #pragma unroll
                for (int e = 0; e < 4; e++) s[np][e] *= SCL;
        }

        // ---- warp-local softmax ----
        float rm0 = -1e30f, rm1 = -1e30f;
        #pragma unroll
        for (int np = 0; np < 8; np++) {
            rm0 = fmaxf(rm0, fmaxf(s[np][0], s[np][1]));
            rm1 = fmaxf(rm1, fmaxf(s[np][2], s[np][3]));
        }
        rm0 = fmaxf(rm0, __shfl_xor_sync(0xffffffffu, rm0, 1));
        rm0 = fmaxf(rm0, __shfl_xor_sync(0xffffffffu, rm0, 2));
        rm1 = fmaxf(rm1, __shfl_xor_sync(0xffffffffu, rm1, 1));
        rm1 = fmaxf(rm1, __shfl_xor_sync(0xffffffffu, rm1, 2));
        const float mn0 = fmaxf(m0f, rm0);
        const float mn1 = fmaxf(m1f, rm1);

        float rs0 = 0.0f, rs1 = 0.0f;
        #pragma unroll
        for (int np = 0; np < 8; np++) {
            s[np][0] = exp2f(s[np][0] - mn0);
            s[np][1] = exp2f(s[np][1] - mn0);
            s[np][2] = exp2f(s[np][2] - mn1);
            s[np][3] = exp2f(s[np][3] - mn1);
            rs0 += s[np][0] + s[np][1];
            rs1 += s[np][2] + s[np][3];
        }
        rs0 += __shfl_xor_sync(0xffffffffu, rs0, 1);
        rs0 += __shfl_xor_sync(0xffffffffu, rs0, 2);
        rs1 += __shfl_xor_sync(0xffffffffu, rs1, 1);
        rs1 += __shfl_xor_sync(0xffffffffu, rs1, 2);

        {
            const float f0 = exp2f(m0f - mn0);
            const float f1 = exp2f(m1f - mn1);
            l0f = l0f * f0 + rs0;  m0f = mn0;
            l1f = l1f * f1 + rs1;  m1f = mn1;
            #pragma unroll
            for (int np = 0; np < 8; np++) {
                o[np][0] *= f0; o[np][1] *= f0;
                o[np][2] *= f1; o[np][3] *= f1;
            }
        }

        // ---- O += P V : P from registers (C-frag == A-frag layout) ----
        #pragma unroll
        for (int ks = 0; ks < 4; ks++) {
            // hi/lo split of P fragments for k-rows ks*16..+15
            float p00 = s[2 * ks][0],     p01 = s[2 * ks][1];
            float p02 = s[2 * ks][2],     p03 = s[2 * ks][3];
            float p10 = s[2 * ks + 1][0], p11 = s[2 * ks + 1][1];
            float p12 = s[2 * ks + 1][2], p13 = s[2 * ks + 1][3];
            float h00 = bfround(p00), h01 = bfround(p01);
            float h02 = bfround(p02), h03 = bfround(p03);
            float h10 = bfround(p10), h11 = bfround(p11);
            float h12 = bfround(p12), h13 = bfround(p13);
            uint32_t pah[4] = { bfpack(h00, h01), bfpack(h02, h03),
                                bfpack(h10, h11), bfpack(h12, h13) };
            uint32_t pal[4] = { bfpack(p00 - h00, p01 - h01),
                                bfpack(p02 - h02, p03 - h03),
                                bfpack(p10 - h10, p11 - h11),
                                bfpack(p12 - h12, p13 - h13) };
            #pragma unroll
            for (int ng = 0; ng < 4; ng++) {
                int nb = ng * 16;
                int krow = ks * 16 + ((g & 1) << 3) + lr;
                uint32_t off = sw128((uint32_t)(krow * 128
                                                + (nb + ((g >> 1) << 3)) * 2));
                uint32_t bh[4], bl[4];
                ldmx4t(bh, vh + off);
                ldmx4t(bl, vl + off);
                mma_bf16(o[ng * 2],     pah, bh[0], bh[1]);
                mma_bf16(o[ng * 2],     pal, bh[0], bh[1]);
                mma_bf16(o[ng * 2],     pah, bl[0], bl[1]);
                mma_bf16(o[ng * 2 + 1], pah, bh[2], bh[3]);
                mma_bf16(o[ng * 2 + 1], pal, bh[2], bh[3]);
                mma_bf16(o[ng * 2 + 1], pah, bl[2], bl[3]);
            }
        }

        if (ck < qt) cpasync_wait0();
        __syncthreads();   // stage safe for next iteration's prefetch
    }

    // ---- epilogue: O /= l, write out ----
    {
        const float inv0 = 1.0f / l0f;
        const float inv1 = 1.0f / l1f;
        const size_t orow = (size_t)b * Sq + (size_t)qt * 64;
        #pragma unroll
        for (int np = 0; np < 8; np++) {
            int hcol = np * 8 + cc;
            float2 v0 = { o[np][0] * inv0, o[np][1] * inv0 };
            float2 v1 = { o[np][2] * inv1, o[np][3] * inv1 };
            *(float2*)&out[(orow + rowA) * Hq + hcol] = v0;
            *(float2*)&out[(orow + rowA + 8) * Hq + hcol] = v1;
        }
    }
}

// ============================================================================
extern "C" void kernel_launch(void* const* d_in, const int* in_sizes, int n_in,
                              void* d_out, int out_size)
{
    const float* x  = (const float*)d_in[0];
    const float* Wq = (const float*)d_in[1];
    const float* Wk = (const float*)d_in[2];
    const float* Wv = (const float*)d_in[3];
    float* out = (float*)d_out;

    cudaFuncSetAttribute(qkv_kernel, cudaFuncAttributeMaxDynamicSharedMemorySize,
                         QKV_SMEM);
    cudaFuncSetAttribute(attn_kernel, cudaFuncAttributeMaxDynamicSharedMemorySize,
                         ATTN_SMEM);

    wprep_kernel<<<96, 512>>>(Wq, Wk, Wv);
    qkv_kernel<<<128, 256, QKV_SMEM>>>(x);
    attn_kernel<<<dim3(64, 4), 128, ATTN_SMEM>>>(out);
}

// round 12
// speedup vs baseline: 1.2783x; 1.2783x over previous
#include <cuda_runtime.h>
#include <cuda_bf16.h>
#include <cstdint>

#define Bq 4
#define Sq 4096
#define Eq 1024
#define Hq 64

// bf16 hi/lo split Q,K,V scratch (qkv_kernel -> attn_kernel)
__device__ __nv_bfloat16 g_Qh[Bq * Sq * Hq];
__device__ __nv_bfloat16 g_Ql[Bq * Sq * Hq];
__device__ __nv_bfloat16 g_Kh[Bq * Sq * Hq];
__device__ __nv_bfloat16 g_Kl[Bq * Sq * Hq];
__device__ __nv_bfloat16 g_Vh[Bq * Sq * Hq];
__device__ __nv_bfloat16 g_Vl[Bq * Sq * Hq];
// pre-converted weights, [w][k][n] bf16 hi/lo
__device__ __nv_bfloat16 g_Wh[3 * Eq * Hq];
__device__ __nv_bfloat16 g_Wl[3 * Eq * Hq];
// split-kv partials: per (batch, qtile, span): unnormalized O + row stats
__device__ float g_pO[Bq * 64 * 2 * 64 * 64];   // 8 MB
__device__ float g_pM[Bq * 64 * 2 * 64];
__device__ float g_pL[Bq * 64 * 2 * 64];

// ---- cp.async helpers ----
__device__ __forceinline__ void cpasync16(uint32_t dst, const void* src) {
    asm volatile("cp.async.cg.shared.global [%0], [%1], 16;" :: "r"(dst), "l"(src));
}
__device__ __forceinline__ void cpasync_commit() {
    asm volatile("cp.async.commit_group;");
}
__device__ __forceinline__ void cpasync_wait0() {
    asm volatile("cp.async.wait_group 0;");
}

// SW128-style swizzle on byte offsets within 128B-row bf16 tiles
__device__ __forceinline__ uint32_t sw128(uint32_t byte_off) {
    return byte_off ^ ((byte_off >> 3) & 0x70);
}

// ---- warp-level MMA helpers ----
__device__ __forceinline__ void ldmx4(uint32_t* r, uint32_t addr) {
    asm volatile("ldmatrix.sync.aligned.m8n8.x4.shared.b16 {%0,%1,%2,%3}, [%4];"
                 : "=r"(r[0]), "=r"(r[1]), "=r"(r[2]), "=r"(r[3]) : "r"(addr));
}
__device__ __forceinline__ void ldmx4t(uint32_t* r, uint32_t addr) {
    asm volatile("ldmatrix.sync.aligned.m8n8.x4.trans.shared.b16 {%0,%1,%2,%3}, [%4];"
                 : "=r"(r[0]), "=r"(r[1]), "=r"(r[2]), "=r"(r[3]) : "r"(addr));
}
__device__ __forceinline__ void mma_bf16(float* c, const uint32_t* a,
                                         uint32_t b0, uint32_t b1) {
    asm volatile(
        "mma.sync.aligned.m16n8k16.row.col.f32.bf16.bf16.f32 "
        "{%0,%1,%2,%3}, {%4,%5,%6,%7}, {%8,%9}, {%0,%1,%2,%3};"
        : "+f"(c[0]), "+f"(c[1]), "+f"(c[2]), "+f"(c[3])
        : "r"(a[0]), "r"(a[1]), "r"(a[2]), "r"(a[3]), "r"(b0), "r"(b1));
}
__device__ __forceinline__ uint32_t bfpack(float a, float b) {
    uint32_t r;
    asm("cvt.rn.bf16x2.f32 %0, %1, %2;" : "=r"(r) : "f"(b), "f"(a));
    return r;
}
__device__ __forceinline__ float bfround(float a) {
    return __bfloat162float(__float2bfloat16(a));
}

// ============================================================================
// Kernel 0: one-time W fp32 -> bf16 hi/lo, [w][k][n]. One float4 per thread.
// ============================================================================
__global__ __launch_bounds__(512) void wprep_kernel(
    const float* __restrict__ Wq, const float* __restrict__ Wk,
    const float* __restrict__ Wv)
{
    const float* Ws[3] = { Wq, Wk, Wv };
    int i = blockIdx.x * 512 + threadIdx.x;       // 0..49151 float4 slots
    int w = i / (Eq * Hq / 4);
    int rem = i - w * (Eq * Hq / 4);
    int k = rem >> 4;
    int n = (rem & 15) * 4;
    float4 v = *(const float4*)&Ws[w][(size_t)k * Hq + n];
    float h0 = bfround(v.x), h1 = bfround(v.y), h2 = bfround(v.z), h3 = bfround(v.w);
    uint2 hv = { bfpack(h0, h1), bfpack(h2, h3) };
    uint2 lv = { bfpack(v.x - h0, v.y - h1), bfpack(v.z - h2, v.w - h3) };
    size_t o = (size_t)w * Eq * Hq + (size_t)k * Hq + n;
    *(uint2*)&g_Wh[o] = hv;
    *(uint2*)&g_Wl[o] = lv;
}

// ============================================================================
// Kernel 1: fused QKV projection via HMMA bf16 3-term split (unchanged).
// ============================================================================
#define QKV_SMEM 81920

__global__ __launch_bounds__(256, 1)
void qkv_kernel(const float* __restrict__ x)
{
    extern __shared__ char qsm[];
    char* Ahi = qsm;
    char* Alo = qsm + 16384;
    const uint32_t uAhi = (uint32_t)__cvta_generic_to_shared(Ahi);
    const uint32_t uAlo = (uint32_t)__cvta_generic_to_shared(Alo);
    const uint32_t uBhi = uAhi + 32768;
    const uint32_t uBlo = uAhi + 57344;

    const int tid    = threadIdx.x;
    const int wid    = tid >> 5;
    const int lane   = tid & 31;
    const int m0     = blockIdx.x * 128;
    const int warp_m = wid & 3;
    const int warp_n = wid >> 2;
    const int g  = lane >> 3;
    const int lr = lane & 7;

    float c[2][12][4];
    #pragma unroll
    for (int mt = 0; mt < 2; mt++)
        #pragma unroll
        for (int nt = 0; nt < 12; nt++)
            #pragma unroll
            for (int e = 0; e < 4; e++) c[mt][nt][e] = 0.0f;

    #pragma unroll 1
    for (int ch = 0; ch < 16; ch++) {
        const int k0 = ch * 64;

        #pragma unroll
        for (int it = 0; it < 6; it++) {
            int cidx = tid + it * 256;
            int w   = cidx >> 9;
            int r   = (cidx >> 3) & 63;
            int c16 = cidx & 7;
            uint32_t off = (uint32_t)(w * 8192) + sw128((uint32_t)(r * 128 + c16 * 16));
            size_t src = (size_t)w * Eq * Hq + (size_t)(k0 + r) * Hq + c16 * 8;
            cpasync16(uBhi + off, g_Wh + src);
            cpasync16(uBlo + off, g_Wl + src);
        }
        cpasync_commit();

        {
            float2 va[16];
            #pragma unroll
            for (int i = 0; i < 16; i++) {
                int p = tid + i * 256;
                int r = p >> 5, k = (p & 31) * 2;
                va[i] = *(const float2*)&x[(size_t)(m0 + r) * Eq + k0 + k];
            }
            #pragma unroll
            for (int i = 0; i < 16; i++) {
                int p = tid + i * 256;
                int r = p >> 5, k = (p & 31) * 2;
                float h0 = bfround(va[i].x), h1 = bfround(va[i].y);
                uint32_t off = sw128((uint32_t)(r * 128 + k * 2));
                *(uint32_t*)(Ahi + off) = bfpack(h0, h1);
                *(uint32_t*)(Alo + off) = bfpack(va[i].x - h0, va[i].y - h1);
            }
        }
        cpasync_wait0();
        __syncthreads();

        #pragma unroll
        for (int ks = 0; ks < 4; ks++) {
            uint32_t ah[2][4], al[2][4];
            #pragma unroll
            for (int mt = 0; mt < 2; mt++) {
                int row = warp_m * 32 + mt * 16 + lr + ((g & 1) << 3);
                uint32_t off = sw128((uint32_t)(row * 128 + ((g >> 1) << 4) + ks * 32));
                ldmx4(ah[mt], uAhi + off);
                ldmx4(al[mt], uAlo + off);
            }
            #pragma unroll
            for (int np = 0; np < 6; np++) {
                const int nglob = warp_n * 96 + np * 16;
                const int w     = nglob >> 6;
                const int ncol  = nglob & 63;
                int krow = ks * 16 + ((g & 1) << 3) + lr;
                uint32_t off = sw128((uint32_t)(krow * 128 + (ncol + ((g >> 1) << 3)) * 2));
                uint32_t bh[4], bl[4];
                ldmx4t(bh, uBhi + w * 8192 + off);
                ldmx4t(bl, uBlo + w * 8192 + off);
                #pragma unroll
                for (int mt = 0; mt < 2; mt++) {
                    mma_bf16(c[mt][np * 2],     ah[mt], bh[0], bh[1]);
                    mma_bf16(c[mt][np * 2],     al[mt], bh[0], bh[1]);
                    mma_bf16(c[mt][np * 2],     ah[mt], bl[0], bl[1]);
                    mma_bf16(c[mt][np * 2 + 1], ah[mt], bh[2], bh[3]);
                    mma_bf16(c[mt][np * 2 + 1], al[mt], bh[2], bh[3]);
                    mma_bf16(c[mt][np * 2 + 1], ah[mt], bl[2], bl[3]);
                }
            }
        }
        __syncthreads();
    }

    {
        __nv_bfloat16* outsH[3] = { g_Qh, g_Kh, g_Vh };
        __nv_bfloat16* outsL[3] = { g_Ql, g_Kl, g_Vl };
        const int crow = lane >> 2;
        const int ccol = (lane & 3) * 2;
        #pragma unroll
        for (int nt = 0; nt < 12; nt++) {
            const int nglob = warp_n * 96 + nt * 8 + ccol;
            __nv_bfloat16* dh = outsH[nglob >> 6];
            __nv_bfloat16* dl = outsL[nglob >> 6];
            const int h = nglob & 63;
            #pragma unroll
            for (int mt = 0; mt < 2; mt++) {
                const int mrow = m0 + warp_m * 32 + mt * 16 + crow;
                #pragma unroll
                for (int rr = 0; rr < 2; rr++) {
                    float v0 = c[mt][nt][rr * 2 + 0];
                    float v1 = c[mt][nt][rr * 2 + 1];
                    float h0 = bfround(v0), h1 = bfround(v1);
                    size_t o = (size_t)(mrow + rr * 8) * Hq + h;
                    *(uint32_t*)&dh[o] = bfpack(h0, h1);
                    *(uint32_t*)&dl[o] = bfpack(v0 - h0, v1 - h1);
                }
            }
        }
    }
}

// ============================================================================
// Kernel 2: causal flash attention, warp-local HMMA + split-kv.
// Flat grid 512: i -> qt = 63-(i>>3) (largest first), b = (i>>1)&3, span = i&1.
// Span 0: kv chunks [0, half); span 1: [half, qt+1), half = ceil((qt+1)/2).
// Max 32 chunk-iters per CTA; 2 CTAs/SM (80KB) -> 8 warps/SM.
// Partials (unnormalized O, m, l) -> scratch; combine_kernel finishes.
// ============================================================================
#define ATTN_SMEM 81920

__global__ __launch_bounds__(128, 2) void attn_kernel()
{
    extern __shared__ char smb[];
    const uint32_t base = (uint32_t)__cvta_generic_to_shared(smb);
    const uint32_t uQH = base, uQL = base + 8192;

    const int tid  = threadIdx.x;
    const int lane = tid & 31;
    const int wid  = tid >> 5;
    const int g    = lane >> 3;
    const int lr   = lane & 7;
    const int r0   = lane >> 2;
    const int cc   = (lane & 3) * 2;

    const int i    = (int)blockIdx.x;
    const int qt   = 63 - (i >> 3);
    const int b    = (i >> 1) & 3;
    const int span = i & 1;
    const int half = (qt + 2) >> 1;            // ceil((qt+1)/2)
    const int lo   = span ? half : 0;
    const int hi   = span ? (qt + 1) : half;

    const int rowA = wid * 16 + r0;

    const size_t qoff   = ((size_t)b * Sq + (size_t)qt * 64) * Hq;
    const size_t kvbase = (size_t)b * Sq * Hq;

    // ---- prologue: Q hi/lo + kv chunk `lo` into stage (lo&1) ----
    {
        const uint32_t st0 = base + 16384 + (uint32_t)(lo & 1) * 32768;
        const size_t ksrc = kvbase + (size_t)lo * 64 * Hq;
        #pragma unroll
        for (int it = 0; it < 4; it++) {
            int chunk = tid + it * 128;
            int r = chunk >> 3, c16 = chunk & 7;
            uint32_t off = sw128((uint32_t)(r * 128 + c16 * 16));
            size_t gsrc = (size_t)r * 64 + c16 * 8;
            cpasync16(uQH + off, g_Qh + qoff + gsrc);
            cpasync16(uQL + off, g_Ql + qoff + gsrc);
            cpasync16(st0 +     0 + off, g_Kh + ksrc + gsrc);
            cpasync16(st0 +  8192 + off, g_Kl + ksrc + gsrc);
            cpasync16(st0 + 16384 + off, g_Vh + ksrc + gsrc);
            cpasync16(st0 + 24576 + off, g_Vl + ksrc + gsrc);
        }
    }
    cpasync_commit();
    cpasync_wait0();
    __syncthreads();

    // ---- hoist Q fragments ----
    uint32_t qh[4][4], ql[4][4];
    #pragma unroll
    for (int ks = 0; ks < 4; ks++) {
        int row = wid * 16 + lr + ((g & 1) << 3);
        uint32_t off = sw128((uint32_t)(row * 128 + ((g >> 1) << 4) + ks * 32));
        ldmx4(qh[ks], uQH + off);
        ldmx4(ql[ks], uQL + off);
    }

    float m0f = -1e30f, m1f = -1e30f, l0f = 0.0f, l1f = 0.0f;
    float o[8][4];
    #pragma unroll
    for (int np = 0; np < 8; np++)
        #pragma unroll
        for (int e = 0; e < 4; e++) o[np][e] = 0.0f;

    const float SCL = 0.125f * 1.44269504089f;

    #pragma unroll 1
    for (int ck = lo; ck < hi; ck++) {
        const uint32_t st = base + 16384 + (uint32_t)(ck & 1) * 32768;
        const uint32_t kh = st, kl = st + 8192, vh = st + 16384, vl = st + 24576;

        if (ck + 1 < hi) {   // prefetch next chunk into alternate stage
            const uint32_t sn = base + 16384 + (uint32_t)(1 - (ck & 1)) * 32768;
            size_t nsrc = kvbase + (size_t)(ck + 1) * 64 * Hq;
            #pragma unroll
            for (int it = 0; it < 4; it++) {
                int chunk = tid + it * 128;
                int r = chunk >> 3, c16 = chunk & 7;
                uint32_t off = sw128((uint32_t)(r * 128 + c16 * 16));
                size_t gsrc = (size_t)r * 64 + c16 * 8;
                cpasync16(sn +     0 + off, g_Kh + nsrc + gsrc);
                cpasync16(sn +  8192 + off, g_Kl + nsrc + gsrc);
                cpasync16(sn + 16384 + off, g_Vh + nsrc + gsrc);
                cpasync16(sn + 24576 + off, g_Vl + nsrc + gsrc);
            }
            cpasync_commit();
        }

        // ---- S = Q K^T ----
        float s[8][4];
        #pragma unroll
        for (int np = 0; np < 8; np++)
            #pragma unroll
            for (int e = 0; e < 4; e++) s[np][e] = 0.0f;

        #pragma unroll
        for (int ks = 0; ks < 4; ks++) {
            #pragma unroll
            for (int ng = 0; ng < 4; ng++) {
                int nrow = ng * 16 + ((g >> 1) << 3) + lr;
                uint32_t off = sw128((uint32_t)(nrow * 128 + ((g & 1) << 4) + ks * 32));
                uint32_t bh[4], bl[4];
                ldmx4(bh, kh + off);
                ldmx4(bl, kl + off);
                mma_bf16(s[ng * 2],     qh[ks], bh[0], bh[1]);
                mma_bf16(s[ng * 2],     ql[ks], bh[0], bh[1]);
                mma_bf16(s[ng * 2],     qh[ks], bl[0], bl[1]);
                mma_bf16(s[ng * 2 + 1], qh[ks], bh[2], bh[3]);
                mma_bf16(s[ng * 2 + 1], ql[ks], bh[2], bh[3]);
                mma_bf16(s[ng * 2 + 1], qh[ks], bl[2], bl[3]);
            }
        }

        // ---- scale + causal mask (diagonal chunk only) ----
        if (ck == qt) {
            const int gi0 = rowA;
            const int gi1 = rowA + 8;
            #pragma unroll
            for (int np = 0; np < 8; np++) {
                int gj = np * 8 + cc;
                s[np][0] = (gj     > gi0) ? -1e30f : s[np][0] * SCL;
                s[np][1] = (gj + 1 > gi0) ? -1e30f : s[np][1] * SCL;
                s[np][2] = (gj     > gi1) ? -1e30f : s[np][2] * SCL;
                s[np][3] = (gj + 1 > gi1) ? -1e30f : s[np][3] * SCL;
            }
        } else {
            #pragma unroll
            for (int np = 0; np < 8; np++)
                #pragma unroll
                for (int e = 0; e < 4; e++) s[np][e] *= SCL;
        }

        // ---- warp-local softmax ----
        float rm0 = -1e30f, rm1 = -1e30f;
        #pragma unroll
        for (int np = 0; np < 8; np++) {
            rm0 = fmaxf(rm0, fmaxf(s[np][0], s[np][1]));
            rm1 = fmaxf(rm1, fmaxf(s[np][2], s[np][3]));
        }
        rm0 = fmaxf(rm0, __shfl_xor_sync(0xffffffffu, rm0, 1));
        rm0 = fmaxf(rm0, __shfl_xor_sync(0xffffffffu, rm0, 2));
        rm1 = fmaxf(rm1, __shfl_xor_sync(0xffffffffu, rm1, 1));
        rm1 = fmaxf(rm1, __shfl_xor_sync(0xffffffffu, rm1, 2));
        const float mn0 = fmaxf(m0f, rm0);
        const float mn1 = fmaxf(m1f, rm1);

        float rs0 = 0.0f, rs1 = 0.0f;
        #pragma unroll
        for (int np = 0; np < 8; np++) {
            s[np][0] = exp2f(s[np][0] - mn0);
            s[np][1] = exp2f(s[np][1] - mn0);
            s[np][2] = exp2f(s[np][2] - mn1);
            s[np][3] = exp2f(s[np][3] - mn1);
            rs0 += s[np][0] + s[np][1];
            rs1 += s[np][2] + s[np][3];
        }
        rs0 += __shfl_xor_sync(0xffffffffu, rs0, 1);
        rs0 += __shfl_xor_sync(0xffffffffu, rs0, 2);
        rs1 += __shfl_xor_sync(0xffffffffu, rs1, 1);
        rs1 += __shfl_xor_sync(0xffffffffu, rs1, 2);

        {
            const float f0 = exp2f(m0f - mn0);
            const float f1 = exp2f(m1f - mn1);
            l0f = l0f * f0 + rs0;  m0f = mn0;
            l1f = l1f * f1 + rs1;  m1f = mn1;
            #pragma unroll
            for (int np = 0; np < 8; np++) {
                o[np][0] *= f0; o[np][1] *= f0;
                o[np][2] *= f1; o[np][3] *= f1;
            }
        }

        // ---- O += P V (P from registers; C-frag == A-frag layout) ----
        #pragma unroll
        for (int ks = 0; ks < 4; ks++) {
            float p00 = s[2 * ks][0],     p01 = s[2 * ks][1];
            float p02 = s[2 * ks][2],     p03 = s[2 * ks][3];
            float p10 = s[2 * ks + 1][0], p11 = s[2 * ks + 1][1];
            float p12 = s[2 * ks + 1][2], p13 = s[2 * ks + 1][3];
            float h00 = bfround(p00), h01 = bfround(p01);
            float h02 = bfround(p02), h03 = bfround(p03);
            float h10 = bfround(p10), h11 = bfround(p11);
            float h12 = bfround(p12), h13 = bfround(p13);
            uint32_t pah[4] = { bfpack(h00, h01), bfpack(h02, h03),
                                bfpack(h10, h11), bfpack(h12, h13) };
            uint32_t pal[4] = { bfpack(p00 - h00, p01 - h01),
                                bfpack(p02 - h02, p03 - h03),
                                bfpack(p10 - h10, p11 - h11),
                                bfpack(p12 - h12, p13 - h13) };
            #pragma unroll
            for (int ng = 0; ng < 4; ng++) {
                int nb = ng * 16;
                int krow = ks * 16 + ((g & 1) << 3) + lr;
                uint32_t off = sw128((uint32_t)(krow * 128
                                                + (nb + ((g >> 1) << 3)) * 2));
                uint32_t bh[4], bl[4];
                ldmx4t(bh, vh + off);
                ldmx4t(bl, vl + off);
                mma_bf16(o[ng * 2],     pah, bh[0], bh[1]);
                mma_bf16(o[ng * 2],     pal, bh[0], bh[1]);
                mma_bf16(o[ng * 2],     pah, bl[0], bl[1]);
                mma_bf16(o[ng * 2 + 1], pah, bh[2], bh[3]);
                mma_bf16(o[ng * 2 + 1], pal, bh[2], bh[3]);
                mma_bf16(o[ng * 2 + 1], pah, bl[2], bl[3]);
            }
        }

        if (ck + 1 < hi) cpasync_wait0();
        __syncthreads();
    }

    // ---- epilogue: write unnormalized partial O + (m, l) ----
    {
        const int sIdx = (b * 64 + qt) * 2 + span;
        float* pO = g_pO + (size_t)sIdx * 4096;
        #pragma unroll
        for (int np = 0; np < 8; np++) {
            int hcol = np * 8 + cc;
            float2 v0 = { o[np][0], o[np][1] };
            float2 v1 = { o[np][2], o[np][3] };
            *(float2*)&pO[rowA * 64 + hcol] = v0;
            *(float2*)&pO[(rowA + 8) * 64 + hcol] = v1;
        }
        if ((lane & 3) == 0) {
            g_pM[sIdx * 64 + rowA]     = m0f;
            g_pL[sIdx * 64 + rowA]     = l0f;
            g_pM[sIdx * 64 + rowA + 8] = m1f;
            g_pL[sIdx * 64 + rowA + 8] = l1f;
        }
    }
}

// ============================================================================
// Kernel 3: combine the two kv-span partials per q-tile, normalize, write out.
// Grid (64, 4), 256 threads: thread owns (row = tid>>2, 16 cols).
// ============================================================================
__global__ __launch_bounds__(256) void combine_kernel(float* __restrict__ out)
{
    const int qt = blockIdx.x, b = blockIdx.y;
    const int tid = threadIdx.x;
    const int row = tid >> 2;
    const int cg  = tid & 3;

    const int sBase = (b * 64 + qt) * 2;
    const float m1 = g_pM[(sBase + 0) * 64 + row];
    const float l1 = g_pL[(sBase + 0) * 64 + row];
    const float m2 = g_pM[(sBase + 1) * 64 + row];
    const float l2 = g_pL[(sBase + 1) * 64 + row];
    const float m  = fmaxf(m1, m2);
    const float e1 = exp2f(m1 - m);
    const float e2 = exp2f(m2 - m);
    const float inv = 1.0f / (l1 * e1 + l2 * e2);

    const float* p1 = g_pO + (size_t)(sBase + 0) * 4096 + row * 64;
    const float* p2 = g_pO + (size_t)(sBase + 1) * 4096 + row * 64;
    float* dst = out + ((size_t)b * Sq + (size_t)qt * 64 + row) * Hq;

    #pragma unroll
    for (int c4 = 0; c4 < 4; c4++) {
        int col = cg * 16 + c4 * 4;
        float4 a  = *(const float4*)&p1[col];
        float4 bb = *(const float4*)&p2[col];
        float4 r;
        r.x = (a.x * e1 + bb.x * e2) * inv;
        r.y = (a.y * e1 + bb.y * e2) * inv;
        r.z = (a.z * e1 + bb.z * e2) * inv;
        r.w = (a.w * e1 + bb.w * e2) * inv;
        *(float4*)&dst[col] = r;
    }
}

// ============================================================================
extern "C" void kernel_launch(void* const* d_in, const int* in_sizes, int n_in,
                              void* d_out, int out_size)
{
    const float* x  = (const float*)d_in[0];
    const float* Wq = (const float*)d_in[1];
    const float* Wk = (const float*)d_in[2];
    const float* Wv = (const float*)d_in[3];
    float* out = (float*)d_out;

    cudaFuncSetAttribute(qkv_kernel, cudaFuncAttributeMaxDynamicSharedMemorySize,
                         QKV_SMEM);
    cudaFuncSetAttribute(attn_kernel, cudaFuncAttributeMaxDynamicSharedMemorySize,
                         ATTN_SMEM);

    wprep_kernel<<<96, 512>>>(Wq, Wk, Wv);
    qkv_kernel<<<128, 256, QKV_SMEM>>>(x);
    attn_kernel<<<512, 128, ATTN_SMEM>>>();
    combine_kernel<<<dim3(64, 4), 256>>>(out);
}

// round 14
// speedup vs baseline: 1.4766x; 1.1551x over previous
#include <cuda_runtime.h>
#include <cuda_bf16.h>
#include <cstdint>

#define Bq 4
#define Sq 4096
#define Eq 1024
#define Hq 64

// bf16 hi/lo split Q,K,V scratch (qkv_kernel -> attn_kernel); Q pre-scaled
__device__ __nv_bfloat16 g_Qh[Bq * Sq * Hq];
__device__ __nv_bfloat16 g_Ql[Bq * Sq * Hq];
__device__ __nv_bfloat16 g_Kh[Bq * Sq * Hq];
__device__ __nv_bfloat16 g_Kl[Bq * Sq * Hq];
__device__ __nv_bfloat16 g_Vh[Bq * Sq * Hq];
__device__ __nv_bfloat16 g_Vl[Bq * Sq * Hq];
// pre-converted weights, [w][k][n] bf16 hi/lo
__device__ __nv_bfloat16 g_Wh[3 * Eq * Hq];
__device__ __nv_bfloat16 g_Wl[3 * Eq * Hq];
// split-kv partials: per (batch, qtile, span): unnormalized O + row stats
__device__ float g_pO[Bq * 64 * 2 * 64 * 64];   // 8 MB
__device__ float g_pM[Bq * 64 * 2 * 64];
__device__ float g_pL[Bq * 64 * 2 * 64];

// ---- cp.async helpers ----
__device__ __forceinline__ void cpasync16(uint32_t dst, const void* src) {
    asm volatile("cp.async.cg.shared.global [%0], [%1], 16;" :: "r"(dst), "l"(src));
}
__device__ __forceinline__ void cpasync_commit() {
    asm volatile("cp.async.commit_group;");
}
__device__ __forceinline__ void cpasync_wait0() {
    asm volatile("cp.async.wait_group 0;");
}

// SW128-style swizzle on byte offsets within 128B-row bf16 tiles
__device__ __forceinline__ uint32_t sw128(uint32_t byte_off) {
    return byte_off ^ ((byte_off >> 3) & 0x70);
}

// ---- warp-level MMA helpers ----
__device__ __forceinline__ void ldmx4(uint32_t* r, uint32_t addr) {
    asm volatile("ldmatrix.sync.aligned.m8n8.x4.shared.b16 {%0,%1,%2,%3}, [%4];"
                 : "=r"(r[0]), "=r"(r[1]), "=r"(r[2]), "=r"(r[3]) : "r"(addr));
}
__device__ __forceinline__ void ldmx4t(uint32_t* r, uint32_t addr) {
    asm volatile("ldmatrix.sync.aligned.m8n8.x4.trans.shared.b16 {%0,%1,%2,%3}, [%4];"
                 : "=r"(r[0]), "=r"(r[1]), "=r"(r[2]), "=r"(r[3]) : "r"(addr));
}
__device__ __forceinline__ void mma_bf16(float* c, const uint32_t* a,
                                         uint32_t b0, uint32_t b1) {
    asm volatile(
        "mma.sync.aligned.m16n8k16.row.col.f32.bf16.bf16.f32 "
        "{%0,%1,%2,%3}, {%4,%5,%6,%7}, {%8,%9}, {%0,%1,%2,%3};"
        : "+f"(c[0]), "+f"(c[1]), "+f"(c[2]), "+f"(c[3])
        : "r"(a[0]), "r"(a[1]), "r"(a[2]), "r"(a[3]), "r"(b0), "r"(b1));
}
__device__ __forceinline__ uint32_t bfpack(float a, float b) {
    uint32_t r;
    asm("cvt.rn.bf16x2.f32 %0, %1, %2;" : "=r"(r) : "f"(b), "f"(a));
    return r;
}
__device__ __forceinline__ float bfround(float a) {
    return __bfloat162float(__float2bfloat16(a));
}

// ============================================================================
// Kernel 0: one-time W fp32 -> bf16 hi/lo, [w][k][n]. One float4 per thread.
// ============================================================================
__global__ __launch_bounds__(512) void wprep_kernel(
    const float* __restrict__ Wq, const float* __restrict__ Wk,
    const float* __restrict__ Wv)
{
    const float* Ws[3] = { Wq, Wk, Wv };
    int i = blockIdx.x * 512 + threadIdx.x;       // 0..49151 float4 slots
    int w = i / (Eq * Hq / 4);
    int rem = i - w * (Eq * Hq / 4);
    int k = rem >> 4;
    int n = (rem & 15) * 4;
    float4 v = *(const float4*)&Ws[w][(size_t)k * Hq + n];
    float h0 = bfround(v.x), h1 = bfround(v.y), h2 = bfround(v.z), h3 = bfround(v.w);
    uint2 hv = { bfpack(h0, h1), bfpack(h2, h3) };
    uint2 lv = { bfpack(v.x - h0, v.y - h1), bfpack(v.z - h2, v.w - h3) };
    size_t o = (size_t)w * Eq * Hq + (size_t)k * Hq + n;
    *(uint2*)&g_Wh[o] = hv;
    *(uint2*)&g_Wl[o] = lv;
}

// ============================================================================
// Kernel 1: fused QKV projection via HMMA bf16 3-term split.
// R12: full double-buffered stages (A + W), one barrier per chunk; the
// next chunk's LDG/cp.async issue before the current chunk's MMA.
// Q outputs pre-scaled by H^-0.5 * log2(e) (softmax scale folded in).
// ============================================================================
#define QKV_STAGE 81920
#define QKV_SMEM  (2 * QKV_STAGE)   // 160 KB, 1 CTA/SM

__global__ __launch_bounds__(256, 1)
void qkv_kernel(const float* __restrict__ x)
{
    extern __shared__ char qsm[];
    const uint32_t uBase = (uint32_t)__cvta_generic_to_shared(qsm);
    // stage s at s*QKV_STAGE: Ahi +0, Alo +16384, Bhi +32768, Blo +57344

    const int tid    = threadIdx.x;
    const int wid    = tid >> 5;
    const int lane   = tid & 31;
    const int m0     = blockIdx.x * 128;
    const int warp_m = wid & 3;
    const int warp_n = wid >> 2;
    const int g  = lane >> 3;
    const int lr = lane & 7;

    float c[2][12][4];
    #pragma unroll
    for (int mt = 0; mt < 2; mt++)
        #pragma unroll
        for (int nt = 0; nt < 12; nt++)
            #pragma unroll
            for (int e = 0; e < 4; e++) c[mt][nt][e] = 0.0f;

    // ---- prologue: fill stage 0 (W cp.async + A convert) ----
    {
        #pragma unroll
        for (int it = 0; it < 6; it++) {
            int cidx = tid + it * 256;
            int w   = cidx >> 9;
            int r   = (cidx >> 3) & 63;
            int c16 = cidx & 7;
            uint32_t off = uBase + 32768 + (uint32_t)(w * 8192)
                         + sw128((uint32_t)(r * 128 + c16 * 16));
            size_t src = (size_t)w * Eq * Hq + (size_t)r * Hq + c16 * 8;
            cpasync16(off, g_Wh + src);
            cpasync16(off + 24576, g_Wl + src);
        }
        cpasync_commit();
        char* Ahi = qsm;
        char* Alo = qsm + 16384;
        #pragma unroll
        for (int i = 0; i < 16; i++) {
            int p = tid + i * 256;
            int r = p >> 5, k = (p & 31) * 2;
            float2 v = *(const float2*)&x[(size_t)(m0 + r) * Eq + k];
            float h0 = bfround(v.x), h1 = bfround(v.y);
            uint32_t off = sw128((uint32_t)(r * 128 + k * 2));
            *(uint32_t*)(Ahi + off) = bfpack(h0, h1);
            *(uint32_t*)(Alo + off) = bfpack(v.x - h0, v.y - h1);
        }
        cpasync_wait0();
        __syncthreads();
    }

    #pragma unroll 1
    for (int ch = 0; ch < 16; ch++) {
        const uint32_t uSt  = uBase + (uint32_t)(ch & 1) * QKV_STAGE;
        const uint32_t uStn = uBase + (uint32_t)(1 - (ch & 1)) * QKV_STAGE;
        const uint32_t uAhi = uSt, uAlo = uSt + 16384;
        const uint32_t uBhi = uSt + 32768, uBlo = uSt + 57344;

        // ---- issue next chunk's x LDGs + W cp.asyncs (overlap with MMA) ----
        float2 va[16];
        if (ch < 15) {
            const int k1 = (ch + 1) * 64;
            #pragma unroll
            for (int i = 0; i < 16; i++) {
                int p = tid + i * 256;
                int r = p >> 5, k = (p & 31) * 2;
                va[i] = *(const float2*)&x[(size_t)(m0 + r) * Eq + k1 + k];
            }
            #pragma unroll
            for (int it = 0; it < 6; it++) {
                int cidx = tid + it * 256;
                int w   = cidx >> 9;
                int r   = (cidx >> 3) & 63;
                int c16 = cidx & 7;
                uint32_t off = uStn + 32768 + (uint32_t)(w * 8192)
                             + sw128((uint32_t)(r * 128 + c16 * 16));
                size_t src = (size_t)w * Eq * Hq + (size_t)(k1 + r) * Hq + c16 * 8;
                cpasync16(off, g_Wh + src);
                cpasync16(off + 24576, g_Wl + src);
            }
            cpasync_commit();
        }

        // ---- MMA on current stage ----
        #pragma unroll
        for (int ks = 0; ks < 4; ks++) {
            uint32_t ah[2][4], al[2][4];
            #pragma unroll
            for (int mt = 0; mt < 2; mt++) {
                int row = warp_m * 32 + mt * 16 + lr + ((g & 1) << 3);
                uint32_t off = sw128((uint32_t)(row * 128 + ((g >> 1) << 4) + ks * 32));
                ldmx4(ah[mt], uAhi + off);
                ldmx4(al[mt], uAlo + off);
            }
            #pragma unroll
            for (int np = 0; np < 6; np++) {
                const int nglob = warp_n * 96 + np * 16;
                const int w     = nglob >> 6;
                const int ncol  = nglob & 63;
                int krow = ks * 16 + ((g & 1) << 3) + lr;
                uint32_t off = sw128((uint32_t)(krow * 128 + (ncol + ((g >> 1) << 3)) * 2));
                uint32_t bh[4], bl[4];
                ldmx4t(bh, uBhi + w * 8192 + off);
                ldmx4t(bl, uBlo + w * 8192 + off);
                #pragma unroll
                for (int mt = 0; mt < 2; mt++) {
                    mma_bf16(c[mt][np * 2],     ah[mt], bh[0], bh[1]);
                    mma_bf16(c[mt][np * 2],     al[mt], bh[0], bh[1]);
                    mma_bf16(c[mt][np * 2],     ah[mt], bl[0], bl[1]);
                    mma_bf16(c[mt][np * 2 + 1], ah[mt], bh[2], bh[3]);
                    mma_bf16(c[mt][np * 2 + 1], al[mt], bh[2], bh[3]);
                    mma_bf16(c[mt][np * 2 + 1], ah[mt], bl[2], bl[3]);
                }
            }
        }

        // ---- convert next A into alternate stage ----
        if (ch < 15) {
            #pragma unroll
            for (int i = 0; i < 16; i++) {
                int p = tid + i * 256;
                int r = p >> 5, k = (p & 31) * 2;
                float h0 = bfround(va[i].x), h1 = bfround(va[i].y);
                uint32_t off = sw128((uint32_t)(r * 128 + k * 2));
                asm volatile("st.shared.b32 [%0], %1;"
                             :: "r"(uStn + off), "r"(bfpack(h0, h1)));
                asm volatile("st.shared.b32 [%0], %1;"
                             :: "r"(uStn + 16384 + off),
                                "r"(bfpack(va[i].x - h0, va[i].y - h1)));
            }
            cpasync_wait0();
        }
        __syncthreads();
    }

    // ---- epilogue: C frags -> bf16 hi/lo global; Q pre-scaled ----
    {
        const float SCLQ = 0.125f * 1.44269504089f;
        __nv_bfloat16* outsH[3] = { g_Qh, g_Kh, g_Vh };
        __nv_bfloat16* outsL[3] = { g_Ql, g_Kl, g_Vl };
        const int crow = lane >> 2;
        const int ccol = (lane & 3) * 2;
        #pragma unroll
        for (int nt = 0; nt < 12; nt++) {
            const int nglob = warp_n * 96 + nt * 8 + ccol;
            const int w = nglob >> 6;
            __nv_bfloat16* dh = outsH[w];
            __nv_bfloat16* dl = outsL[w];
            const float scl = (w == 0) ? SCLQ : 1.0f;
            const int h = nglob & 63;
            #pragma unroll
            for (int mt = 0; mt < 2; mt++) {
                const int mrow = m0 + warp_m * 32 + mt * 16 + crow;
                #pragma unroll
                for (int rr = 0; rr < 2; rr++) {
                    float v0 = c[mt][nt][rr * 2 + 0] * scl;
                    float v1 = c[mt][nt][rr * 2 + 1] * scl;
                    float h0 = bfround(v0), h1 = bfround(v1);
                    size_t o = (size_t)(mrow + rr * 8) * Hq + h;
                    *(uint32_t*)&dh[o] = bfpack(h0, h1);
                    *(uint32_t*)&dl[o] = bfpack(v0 - h0, v1 - h1);
                }
            }
        }
    }
}

// ============================================================================
// Kernel 2: causal flash attention, warp-local HMMA + split-kv.
// Q pre-scaled (no per-iter scale); diagonal chunk does mask only.
// Flat grid 512: i -> qt = 63-(i>>3), b = (i>>1)&3, span = i&1.
// ============================================================================
#define ATTN_SMEM 81920

__global__ __launch_bounds__(128, 2) void attn_kernel()
{
    extern __shared__ char smb[];
    const uint32_t base = (uint32_t)__cvta_generic_to_shared(smb);
    const uint32_t uQH = base, uQL = base + 8192;

    const int tid  = threadIdx.x;
    const int lane = tid & 31;
    const int wid  = tid >> 5;
    const int g    = lane >> 3;
    const int lr   = lane & 7;
    const int r0   = lane >> 2;
    const int cc   = (lane & 3) * 2;

    const int i    = (int)blockIdx.x;
    const int qt   = 63 - (i >> 3);
    const int b    = (i >> 1) & 3;
    const int span = i & 1;
    const int half = (qt + 2) >> 1;
    const int lo   = span ? half : 0;
    const int hi   = span ? (qt + 1) : half;

    const int rowA = wid * 16 + r0;

    const size_t qoff   = ((size_t)b * Sq + (size_t)qt * 64) * Hq;
    const size_t kvbase = (size_t)b * Sq * Hq;

    // ---- prologue: Q hi/lo + kv chunk `lo` into stage (lo&1) ----
    {
        const uint32_t st0 = base + 16384 + (uint32_t)(lo & 1) * 32768;
        const size_t ksrc = kvbase + (size_t)lo * 64 * Hq;
        #pragma unroll
        for (int it = 0; it < 4; it++) {
            int chunk = tid + it * 128;
            int r = chunk >> 3, c16 = chunk & 7;
            uint32_t off = sw128((uint32_t)(r * 128 + c16 * 16));
            size_t gsrc = (size_t)r * 64 + c16 * 8;
            cpasync16(uQH + off, g_Qh + qoff + gsrc);
            cpasync16(uQL + off, g_Ql + qoff + gsrc);
            cpasync16(st0 +     0 + off, g_Kh + ksrc + gsrc);
            cpasync16(st0 +  8192 + off, g_Kl + ksrc + gsrc);
            cpasync16(st0 + 16384 + off, g_Vh + ksrc + gsrc);
            cpasync16(st0 + 24576 + off, g_Vl + ksrc + gsrc);
        }
    }
    cpasync_commit();
    cpasync_wait0();
    __syncthreads();

    // ---- hoist Q fragments ----
    uint32_t qh[4][4], ql[4][4];
    #pragma unroll
    for (int ks = 0; ks < 4; ks++) {
        int row = wid * 16 + lr + ((g & 1) << 3);
        uint32_t off = sw128((uint32_t)(row * 128 + ((g >> 1) << 4) + ks * 32));
        ldmx4(qh[ks], uQH + off);
        ldmx4(ql[ks], uQL + off);
    }

    float m0f = -1e30f, m1f = -1e30f, l0f = 0.0f, l1f = 0.0f;
    float o[8][4];
    #pragma unroll
    for (int np = 0; np < 8; np++)
        #pragma unroll
        for (int e = 0; e < 4; e++) o[np][e] = 0.0f;

    #pragma unroll 1
    for (int ck = lo; ck < hi; ck++) {
        const uint32_t st = base + 16384 + (uint32_t)(ck & 1) * 32768;
        const uint32_t kh = st, kl = st + 8192, vh = st + 16384, vl = st + 24576;

        if (ck + 1 < hi) {
            const uint32_t sn = base + 16384 + (uint32_t)(1 - (ck & 1)) * 32768;
            size_t nsrc = kvbase + (size_t)(ck + 1) * 64 * Hq;
            #pragma unroll
            for (int it = 0; it < 4; it++) {
                int chunk = tid + it * 128;
                int r = chunk >> 3, c16 = chunk & 7;
                uint32_t off = sw128((uint32_t)(r * 128 + c16 * 16));
                size_t gsrc = (size_t)r * 64 + c16 * 8;
                cpasync16(sn +     0 + off, g_Kh + nsrc + gsrc);
                cpasync16(sn +  8192 + off, g_Kl + nsrc + gsrc);
                cpasync16(sn + 16384 + off, g_Vh + nsrc + gsrc);
                cpasync16(sn + 24576 + off, g_Vl + nsrc + gsrc);
            }
            cpasync_commit();
        }

        // ---- S = Q K^T (Q pre-scaled) ----
        float s[8][4];
        #pragma unroll
        for (int np = 0; np < 8; np++)
            #pragma unroll
            for (int e = 0; e < 4; e++) s[np][e] = 0.0f;

        #pragma unroll
        for (int ks = 0; ks < 4; ks++) {
            #pragma unroll
            for (int ng = 0; ng < 4; ng++) {
                int nrow = ng * 16 + ((g >> 1) << 3) + lr;
                uint32_t off = sw128((uint32_t)(nrow * 128 + ((g & 1) << 4) + ks * 32));
                uint32_t bh[4], bl[4];
                ldmx4(bh, kh + off);
                ldmx4(bl, kl + off);
                mma_bf16(s[ng * 2],     qh[ks], bh[0], bh[1]);
                mma_bf16(s[ng * 2],     ql[ks], bh[0], bh[1]);
                mma_bf16(s[ng * 2],     qh[ks], bl[0], bl[1]);
                mma_bf16(s[ng * 2 + 1], qh[ks], bh[2], bh[3]);
                mma_bf16(s[ng * 2 + 1], ql[ks], bh[2], bh[3]);
                mma_bf16(s[ng * 2 + 1], qh[ks], bl[2], bl[3]);
            }
        }

        // ---- causal mask (diagonal chunk only; no scale needed) ----
        if (ck == qt) {
            const int gi0 = rowA;
            const int gi1 = rowA + 8;
            #pragma unroll
            for (int np = 0; np < 8; np++) {
                int gj = np * 8 + cc;
                if (gj     > gi0) s[np][0] = -1e30f;
                if (gj + 1 > gi0) s[np][1] = -1e30f;
                if (gj     > gi1) s[np][2] = -1e30f;
                if (gj + 1 > gi1) s[np][3] = -1e30f;
            }
        }

        // ---- warp-local softmax ----
        float rm0 = -1e30f, rm1 = -1e30f;
        #pragma unroll
        for (int np = 0; np < 8; np++) {
            rm0 = fmaxf(rm0, fmaxf(s[np][0], s[np][1]));
            rm1 = fmaxf(rm1, fmaxf(s[np][2], s[np][3]));
        }
        rm0 = fmaxf(rm0, __shfl_xor_sync(0xffffffffu, rm0, 1));
        rm0 = fmaxf(rm0, __shfl_xor_sync(0xffffffffu, rm0, 2));
        rm1 = fmaxf(rm1, __shfl_xor_sync(0xffffffffu, rm1, 1));
        rm1 = fmaxf(rm1, __shfl_xor_sync(0xffffffffu, rm1, 2));
        const float mn0 = fmaxf(m0f, rm0);
        const float mn1 = fmaxf(m1f, rm1);

        float rs0 = 0.0f, rs1 = 0.0f;
        #pragma unroll
        for (int np = 0; np < 8; np++) {
            s[np][0] = exp2f(s[np][0] - mn0);
            s[np][1] = exp2f(s[np][1] - mn0);
            s[np][2] = exp2f(s[np][2] - mn1);
            s[np][3] = exp2f(s[np][3] - mn1);
            rs0 += s[np][0] + s[np][1];
            rs1 += s[np][2] + s[np][3];
        }
        rs0 += __shfl_xor_sync(0xffffffffu, rs0, 1);
        rs0 += __shfl_xor_sync(0xffffffffu, rs0, 2);
        rs1 += __shfl_xor_sync(0xffffffffu, rs1, 1);
        rs1 += __shfl_xor_sync(0xffffffffu, rs1, 2);

        {
            const float f0 = exp2f(m0f - mn0);
            const float f1 = exp2f(m1f - mn1);
            l0f = l0f * f0 + rs0;  m0f = mn0;
            l1f = l1f * f1 + rs1;  m1f = mn1;
            #pragma unroll
            for (int np = 0; np < 8; np++) {
                o[np][0] *= f0; o[np][1] *= f0;
                o[np][2] *= f1; o[np][3] *= f1;
            }
        }

        // ---- O += P V (P from registers) ----
        #pragma unroll
        for (int ks = 0; ks < 4; ks++) {
            float p00 = s[2 * ks][0],     p01 = s[2 * ks][1];
            float p02 = s[2 * ks][2],     p03 = s[2 * ks][3];
            float p10 = s[2 * ks + 1][0], p11 = s[2 * ks + 1][1];
            float p12 = s[2 * ks + 1][2], p13 = s[2 * ks + 1][3];
            float h00 = bfround(p00), h01 = bfround(p01);
            float h02 = bfround(p02), h03 = bfround(p03);
            float h10 = bfround(p10), h11 = bfround(p11);
            float h12 = bfround(p12), h13 = bfround(p13);
            uint32_t pah[4] = { bfpack(h00, h01), bfpack(h02, h03),
                                bfpack(h10, h11), bfpack(h12, h13) };
            uint32_t pal[4] = { bfpack(p00 - h00, p01 - h01),
                                bfpack(p02 - h02, p03 - h03),
                                bfpack(p10 - h10, p11 - h11),
                                bfpack(p12 - h12, p13 - h13) };
            #pragma unroll
            for (int ng = 0; ng < 4; ng++) {
                int nb = ng * 16;
                int krow = ks * 16 + ((g & 1) << 3) + lr;
                uint32_t off = sw128((uint32_t)(krow * 128
                                                + (nb + ((g >> 1) << 3)) * 2));
                uint32_t bh[4], bl[4];
                ldmx4t(bh, vh + off);
                ldmx4t(bl, vl + off);
                mma_bf16(o[ng * 2],     pah, bh[0], bh[1]);
                mma_bf16(o[ng * 2],     pal, bh[0], bh[1]);
                mma_bf16(o[ng * 2],     pah, bl[0], bl[1]);
                mma_bf16(o[ng * 2 + 1], pah, bh[2], bh[3]);
                mma_bf16(o[ng * 2 + 1], pal, bh[2], bh[3]);
                mma_bf16(o[ng * 2 + 1], pah, bl[2], bl[3]);
            }
        }

        if (ck + 1 < hi) cpasync_wait0();
        __syncthreads();
    }

    // ---- epilogue: write unnormalized partial O + (m, l) ----
    {
        const int sIdx = (b * 64 + qt) * 2 + span;
        float* pO = g_pO + (size_t)sIdx * 4096;
        #pragma unroll
        for (int np = 0; np < 8; np++) {
            int hcol = np * 8 + cc;
            float2 v0 = { o[np][0], o[np][1] };
            float2 v1 = { o[np][2], o[np][3] };
            *(float2*)&pO[rowA * 64 + hcol] = v0;
            *(float2*)&pO[(rowA + 8) * 64 + hcol] = v1;
        }
        if ((lane & 3) == 0) {
            g_pM[sIdx * 64 + rowA]     = m0f;
            g_pL[sIdx * 64 + rowA]     = l0f;
            g_pM[sIdx * 64 + rowA + 8] = m1f;
            g_pL[sIdx * 64 + rowA + 8] = l1f;
        }
    }
}

// ============================================================================
// Kernel 3: combine span partials, normalize, write out. 512 threads.
// ============================================================================
__global__ __launch_bounds__(512) void combine_kernel(float* __restrict__ out)
{
    const int qt = blockIdx.x, b = blockIdx.y;
    const int tid = threadIdx.x;
    const int row = tid >> 3;          // 64 rows x 8 col-groups
    const int cg  = tid & 7;

    const int sBase = (b * 64 + qt) * 2;
    const float m1 = g_pM[(sBase + 0) * 64 + row];
    const float l1 = g_pL[(sBase + 0) * 64 + row];
    const float m2 = g_pM[(sBase + 1) * 64 + row];
    const float l2 = g_pL[(sBase + 1) * 64 + row];
    const float m  = fmaxf(m1, m2);
    const float e1 = exp2f(m1 - m);
    const float e2 = exp2f(m2 - m);
    const float inv = 1.0f / (l1 * e1 + l2 * e2);

    const float* p1 = g_pO + (size_t)(sBase + 0) * 4096 + row * 64;
    const float* p2 = g_pO + (size_t)(sBase + 1) * 4096 + row * 64;
    float* dst = out + ((size_t)b * Sq + (size_t)qt * 64 + row) * Hq;

    #pragma unroll
    for (int c4 = 0; c4 < 2; c4++) {
        int col = cg * 8 + c4 * 4;
        float4 a  = *(const float4*)&p1[col];
        float4 bb = *(const float4*)&p2[col];
        float4 r;
        r.x = (a.x * e1 + bb.x * e2) * inv;
        r.y = (a.y * e1 + bb.y * e2) * inv;
        r.z = (a.z * e1 + bb.z * e2) * inv;
        r.w = (a.w * e1 + bb.w * e2) * inv;
        *(float4*)&dst[col] = r;
    }
}

// ============================================================================
extern "C" void kernel_launch(void* const* d_in, const int* in_sizes, int n_in,
                              void* d_out, int out_size)
{
    const float* x  = (const float*)d_in[0];
    const float* Wq = (const float*)d_in[1];
    const float* Wk = (const float*)d_in[2];
    const float* Wv = (const float*)d_in[3];
    float* out = (float*)d_out;

    cudaFuncSetAttribute(qkv_kernel, cudaFuncAttributeMaxDynamicSharedMemorySize,
                         QKV_SMEM);
    cudaFuncSetAttribute(attn_kernel, cudaFuncAttributeMaxDynamicSharedMemorySize,
                         ATTN_SMEM);

    wprep_kernel<<<96, 512>>>(Wq, Wk, Wv);
    qkv_kernel<<<128, 256, QKV_SMEM>>>(x);
    attn_kernel<<<512, 128, ATTN_SMEM>>>();
    combine_kernel<<<dim3(64, 4), 512>>>(out);
}